// round 16
// baseline (speedup 1.0000x reference)
#include <cuda_runtime.h>
#include <cuda_bf16.h>
#include <mma.h>

using namespace nvcuda;

// ---------------- problem constants ----------------
#define BATCH 8
#define SEQ 4096
#define CTX_L 77
#define QDIM 1024
#define CDIM 768
#define HEADS 8
#define DHEAD 64
#define INNER 512          // HEADS * DHEAD

#define MX (BATCH * SEQ)     // 32768
#define MC (BATCH * CTX_L)   // 616

// ---------------- scratch ----------------
__device__ float g_Q[BATCH * SEQ * INNER];      // 64 MiB
__device__ float g_K[BATCH * CTX_L * INNER];
__device__ float g_V[BATCH * CTX_L * INNER];
__device__ float g_A[BATCH * SEQ * INNER];      // 64 MiB

// ---------------- cp.async helpers ----------------
__device__ __forceinline__ unsigned smem_u32(const void* p) {
    return (unsigned)__cvta_generic_to_shared(p);
}
__device__ __forceinline__ void cp16(unsigned s, const void* g) {
    asm volatile("cp.async.cg.shared.global [%0], [%1], 16;\n" :: "r"(s), "l"(g));
}
#define CP_COMMIT() asm volatile("cp.async.commit_group;" ::: "memory")
#define CP_WAIT(n)  asm volatile("cp.async.wait_group %0;" :: "n"(n) : "memory")

// =====================================================================
// FAST GEMM: C[M,N] = A[M,K] @ B[K,N] (+bias). M%128==0, N%256==0,
// K%16==0, K/16>=3. Tile 128x256x16, 512 threads (16 warps, warp tile
// 32x64), 3-stage cp.async, ONE __syncthreads per iteration.
// Dynamic smem: 3*(128*20 + 16*264)*4 = 81408 bytes.
// =====================================================================
#define FBM 128
#define FBN 256
#define FBK 16
#define ALD 20     // A row stride (80B)
#define BLD 264    // B row stride (1056B)
#define A_STAGE (FBM * ALD)   // 2560 floats
#define B_STAGE (FBK * BLD)   // 4224 floats
#define GEMM_SMEM_BYTES ((3 * (A_STAGE + B_STAGE)) * 4)  // 81408

__device__ __forceinline__ void gemm_fast_body(
    const float* __restrict__ A, const float* __restrict__ B,
    float* __restrict__ C, const float* __restrict__ bias,
    int M, int N, int K)
{
    extern __shared__ float dsm[];
    float* As = dsm;                 // [3][128][ALD]
    float* Bs = dsm + 3 * A_STAGE;   // [3][16][BLD]

    const int tid  = threadIdx.x;
    const int warp = tid >> 5;
    const int wm   = warp >> 2;   // 0..3  (32-row strip)
    const int wn   = warp & 3;    // 0..3  (64-col strip)
    const int row0 = blockIdx.y * FBM;
    const int col0 = blockIdx.x * FBN;

    wmma::fragment<wmma::accumulator, 16, 16, 8, float> acc[2][4];
    if (bias) {
        // replicate bias into 16 rows of Bs stage 0, load as acc init
        for (int i = tid; i < 16 * FBN; i += 512) {
            int r = i >> 8, c = i & 255;
            Bs[r * BLD + c] = bias[col0 + c];
        }
        __syncthreads();
#pragma unroll
        for (int i = 0; i < 2; i++)
#pragma unroll
            for (int j = 0; j < 4; j++)
                wmma::load_matrix_sync(acc[i][j], &Bs[wn * 64 + j * 16],
                                       BLD, wmma::mem_row_major);
        __syncthreads();
    } else {
#pragma unroll
        for (int i = 0; i < 2; i++)
#pragma unroll
            for (int j = 0; j < 4; j++)
                wmma::fill_fragment(acc[i][j], 0.0f);
    }

    auto load_stage = [&](int st, int k0) {
        float* Ad = As + st * A_STAGE;
        float* Bd = Bs + st * B_STAGE;
        // A: 128x16 = 512 float4, 1 per thread
        {
            int r = tid >> 2, c4 = (tid & 3) * 4;
            cp16(smem_u32(&Ad[r * ALD + c4]),
                 A + (size_t)(row0 + r) * K + k0 + c4);
        }
        // B: 16x256 = 1024 float4, 2 per thread
#pragma unroll
        for (int i = 0; i < 2; i++) {
            int slot = tid + i * 512;
            int r = slot >> 6, c4 = (slot & 63) * 4;
            cp16(smem_u32(&Bd[r * BLD + c4]),
                 B + (size_t)(k0 + r) * N + col0 + c4);
        }
        CP_COMMIT();
    };

    const int nIter = K / FBK;
    load_stage(0, 0);
    load_stage(1, FBK);

    int st = 0;
    for (int it = 0; it < nIter; ++it) {
        if (it == nIter - 1) { CP_WAIT(0); } else { CP_WAIT(1); }
        __syncthreads();
        if (it + 2 < nIter) {
            int tgt = st + 2; if (tgt >= 3) tgt -= 3;
            load_stage(tgt, (it + 2) * FBK);
        }

        const float* Ab = As + st * A_STAGE;
        const float* Bb = Bs + st * B_STAGE;
#pragma unroll
        for (int kk = 0; kk < 2; kk++) {
            wmma::fragment<wmma::matrix_a, 16, 16, 8, wmma::precision::tf32, wmma::row_major> af[2];
            wmma::fragment<wmma::matrix_b, 16, 16, 8, wmma::precision::tf32, wmma::row_major> bf[4];
            wmma::load_matrix_sync(af[0], &Ab[(wm * 32) * ALD + kk * 8],      ALD);
            wmma::load_matrix_sync(af[1], &Ab[(wm * 32 + 16) * ALD + kk * 8], ALD);
#pragma unroll
            for (int j = 0; j < 4; j++)
                wmma::load_matrix_sync(bf[j], &Bb[(kk * 8) * BLD + wn * 64 + j * 16], BLD);
#pragma unroll
            for (int i = 0; i < 2; i++)
#pragma unroll
                for (int t = 0; t < af[0].num_elements; t++)
                    af[i].x[t] = wmma::__float_to_tf32(af[i].x[t]);
#pragma unroll
            for (int j = 0; j < 4; j++)
#pragma unroll
                for (int t = 0; t < bf[0].num_elements; t++)
                    bf[j].x[t] = wmma::__float_to_tf32(bf[j].x[t]);
#pragma unroll
            for (int i = 0; i < 2; i++)
#pragma unroll
                for (int j = 0; j < 4; j++)
                    wmma::mma_sync(acc[i][j], af[i], bf[j], acc[i][j]);
        }
        if (++st == 3) st = 0;
    }

    // epilogue: fragments straight to GMEM
#pragma unroll
    for (int i = 0; i < 2; i++)
#pragma unroll
        for (int j = 0; j < 4; j++)
            wmma::store_matrix_sync(
                C + (size_t)(row0 + wm * 32 + i * 16) * N + col0 + wn * 64 + j * 16,
                acc[i][j], N, wmma::mem_row_major);
}

__global__ __launch_bounds__(512) void gemm_q_fast(
    const float* __restrict__ x, const float* __restrict__ Wq)
{
    gemm_fast_body(x, Wq, g_Q, nullptr, MX, INNER, QDIM);
}
__global__ __launch_bounds__(512) void gemm_o_fast(
    const float* __restrict__ Wo, const float* __restrict__ bo,
    float* __restrict__ out)
{
    gemm_fast_body(g_A, Wo, out, bo, MX, QDIM, INNER);
}

// =====================================================================
// fused K/V projection (M=616): 64x64x32, 128 threads; blockIdx.z
// selects (Wk -> g_K) or (Wv -> g_V). One launch instead of two.
// =====================================================================
#define GM_BM 64
#define GM_BN 64
#define GM_BK 32
#define GM_PADA 8
#define GM_PADB 8

__global__ __launch_bounds__(128) void gemm_kv_kernel(
    const float* __restrict__ ctx,
    const float* __restrict__ Wk, const float* __restrict__ Wv)
{
    const float* B = blockIdx.z ? Wv : Wk;
    float* C = blockIdx.z ? g_V : g_K;
    const int M = MC, N = INNER, K = CDIM;

    __shared__ float As[GM_BM][GM_BK + GM_PADA];
    __shared__ float Bs[GM_BK][GM_BN + GM_PADB];
    __shared__ float Cs[GM_BM][GM_BN + 4];

    const int tid  = threadIdx.x;
    const int warp = tid >> 5;
    const int wm   = warp >> 1;
    const int wn   = warp & 1;
    const int row0 = blockIdx.y * GM_BM;
    const int col0 = blockIdx.x * GM_BN;

    wmma::fragment<wmma::accumulator, 16, 16, 8, float> acc[2][2];
#pragma unroll
    for (int i = 0; i < 2; i++)
#pragma unroll
        for (int j = 0; j < 2; j++)
            wmma::fill_fragment(acc[i][j], 0.0f);

    for (int k0 = 0; k0 < K; k0 += GM_BK) {
#pragma unroll
        for (int i = 0; i < 4; i++) {
            int slot = tid + i * 128;
            int r = slot >> 3, c4 = (slot & 7) * 4;
            int grow = row0 + r;
            float4 v = make_float4(0.f, 0.f, 0.f, 0.f);
            if (grow < M)
                v = *(const float4*)(ctx + (size_t)grow * K + k0 + c4);
            *(float4*)&As[r][c4] = v;
        }
#pragma unroll
        for (int i = 0; i < 4; i++) {
            int slot = tid + i * 128;
            int r = slot >> 4, c4 = (slot & 15) * 4;
            float4 v = *(const float4*)(B + (size_t)(k0 + r) * N + col0 + c4);
            *(float4*)&Bs[r][c4] = v;
        }
        __syncthreads();

#pragma unroll
        for (int kk = 0; kk < 4; kk++) {
            wmma::fragment<wmma::matrix_a, 16, 16, 8, wmma::precision::tf32, wmma::row_major> a0, a1;
            wmma::fragment<wmma::matrix_b, 16, 16, 8, wmma::precision::tf32, wmma::row_major> b0, b1;
            wmma::load_matrix_sync(a0, &As[wm * 32][kk * 8],      GM_BK + GM_PADA);
            wmma::load_matrix_sync(a1, &As[wm * 32 + 16][kk * 8], GM_BK + GM_PADA);
            wmma::load_matrix_sync(b0, &Bs[kk * 8][wn * 32],      GM_BN + GM_PADB);
            wmma::load_matrix_sync(b1, &Bs[kk * 8][wn * 32 + 16], GM_BN + GM_PADB);
#pragma unroll
            for (int t = 0; t < a0.num_elements; t++) {
                a0.x[t] = wmma::__float_to_tf32(a0.x[t]);
                a1.x[t] = wmma::__float_to_tf32(a1.x[t]);
            }
#pragma unroll
            for (int t = 0; t < b0.num_elements; t++) {
                b0.x[t] = wmma::__float_to_tf32(b0.x[t]);
                b1.x[t] = wmma::__float_to_tf32(b1.x[t]);
            }
            wmma::mma_sync(acc[0][0], a0, b0, acc[0][0]);
            wmma::mma_sync(acc[0][1], a0, b1, acc[0][1]);
            wmma::mma_sync(acc[1][0], a1, b0, acc[1][0]);
            wmma::mma_sync(acc[1][1], a1, b1, acc[1][1]);
        }
        __syncthreads();
    }

#pragma unroll
    for (int i = 0; i < 2; i++)
#pragma unroll
        for (int j = 0; j < 2; j++)
            wmma::store_matrix_sync(&Cs[wm * 32 + i * 16][wn * 32 + j * 16],
                                    acc[i][j], GM_BN + 4, wmma::mem_row_major);
    __syncthreads();

#pragma unroll
    for (int i = 0; i < 8; i++) {
        int slot = tid + i * 128;
        int r = slot >> 4, c4 = (slot & 15) * 4;
        int grow = row0 + r;
        if (grow < M)
            *(float4*)(C + (size_t)grow * N + col0 + c4) = *(float4*)&Cs[r][c4];
    }
}

// =====================================================================
// Tensor-core cross-attention (exact R12 version).
// =====================================================================
#define BQ   64
#define LPAD 96
#define QLD  68
#define SLD  100
#define VLD  36

__global__ __launch_bounds__(256) void attn_wmma_kernel()
{
    __shared__ float sm[10880];
    float* Qs = sm;
    float* Ks = sm + BQ * QLD;
    float* Ss = sm;
    float* Vs = sm + BQ * SLD;

    const int b  = blockIdx.z;
    const int h  = blockIdx.y;
    const int s0 = blockIdx.x * BQ;
    const int tid  = threadIdx.x;
    const int warp = tid >> 5;
    const int wr   = warp >> 1;
    const int wc   = warp & 1;

    for (int idx = tid; idx < BQ * 16; idx += 256) {
        int r = idx >> 4, c4 = (idx & 15) << 2;
        *(float4*)&Qs[r * QLD + c4] =
            *(const float4*)&g_Q[((size_t)(b * SEQ + s0 + r)) * INNER + h * DHEAD + c4];
    }
    for (int idx = tid; idx < CTX_L * 16; idx += 256) {
        int r = idx >> 4, c4 = (idx & 15) << 2;
        *(float4*)&Ks[r * QLD + c4] =
            *(const float4*)&g_K[((size_t)(b * CTX_L + r)) * INNER + h * DHEAD + c4];
    }
    __syncthreads();

    const int ct0 = wc ? 3 : 0;
    const int nct = wc ? 2 : 3;
    wmma::fragment<wmma::accumulator, 16, 16, 8, float> sacc[3];
#pragma unroll
    for (int j = 0; j < 3; j++) wmma::fill_fragment(sacc[j], 0.0f);

#pragma unroll
    for (int k = 0; k < 8; k++) {
        wmma::fragment<wmma::matrix_a, 16, 16, 8, wmma::precision::tf32, wmma::row_major> af;
        wmma::load_matrix_sync(af, &Qs[(wr * 16) * QLD + k * 8], QLD);
#pragma unroll
        for (int t = 0; t < af.num_elements; t++) af.x[t] = wmma::__float_to_tf32(af.x[t]);
#pragma unroll
        for (int j = 0; j < 3; j++) {
            if (j >= nct) break;
            wmma::fragment<wmma::matrix_b, 16, 16, 8, wmma::precision::tf32, wmma::col_major> bf;
            wmma::load_matrix_sync(bf, &Ks[((ct0 + j) * 16) * QLD + k * 8], QLD);
#pragma unroll
            for (int t = 0; t < bf.num_elements; t++) bf.x[t] = wmma::__float_to_tf32(bf.x[t]);
            wmma::mma_sync(sacc[j], af, bf, sacc[j]);
        }
    }
#pragma unroll
    for (int j = 0; j < 3; j++)
#pragma unroll
        for (int t = 0; t < sacc[j].num_elements; t++) sacc[j].x[t] *= 0.125f;

    __syncthreads();
#pragma unroll
    for (int j = 0; j < 3; j++) {
        if (j >= nct) break;
        wmma::store_matrix_sync(&Ss[(wr * 16) * SLD + (ct0 + j) * 16], sacc[j],
                                SLD, wmma::mem_row_major);
    }
    __syncthreads();

    {
        const int row = tid >> 2, p = tid & 3;
        float* srow = &Ss[row * SLD];
        const int c0 = p * 24, c1 = c0 + 24;
        float mx = -1e30f;
        for (int c = c0; c < c1 && c < CTX_L; c++) mx = fmaxf(mx, srow[c]);
        mx = fmaxf(mx, __shfl_xor_sync(0xffffffffu, mx, 1));
        mx = fmaxf(mx, __shfl_xor_sync(0xffffffffu, mx, 2));
        float sum = 0.f;
        float ebuf[24];
#pragma unroll
        for (int i = 0; i < 24; i++) {
            int c = c0 + i;
            float e = (c < CTX_L) ? __expf(srow[c] - mx) : 0.f;
            ebuf[i] = e; sum += e;
        }
        sum += __shfl_xor_sync(0xffffffffu, sum, 1);
        sum += __shfl_xor_sync(0xffffffffu, sum, 2);
        const float inv = 1.f / sum;
#pragma unroll
        for (int i = 0; i < 24; i++) srow[c0 + i] = ebuf[i] * inv;
    }
    __syncthreads();

#pragma unroll
    for (int ch = 0; ch < 2; ch++) {
        for (int idx = tid; idx < CTX_L * 8; idx += 256) {
            int r = idx >> 3, c4 = (idx & 7) << 2;
            *(float4*)&Vs[r * VLD + c4] =
                *(const float4*)&g_V[((size_t)(b * CTX_L + r)) * INNER + h * DHEAD + ch * 32 + c4];
        }
        for (int idx = tid; idx < (LPAD - CTX_L) * 8; idx += 256) {
            int r = CTX_L + (idx >> 3), c4 = (idx & 7) << 2;
            *(float4*)&Vs[r * VLD + c4] = make_float4(0.f, 0.f, 0.f, 0.f);
        }
        __syncthreads();

        wmma::fragment<wmma::accumulator, 16, 16, 8, float> oacc;
        wmma::fill_fragment(oacc, 0.0f);
#pragma unroll
        for (int k = 0; k < LPAD / 8; k++) {
            wmma::fragment<wmma::matrix_a, 16, 16, 8, wmma::precision::tf32, wmma::row_major> af;
            wmma::fragment<wmma::matrix_b, 16, 16, 8, wmma::precision::tf32, wmma::row_major> bf;
            wmma::load_matrix_sync(af, &Ss[(wr * 16) * SLD + k * 8], SLD);
            wmma::load_matrix_sync(bf, &Vs[(k * 8) * VLD + wc * 16], VLD);
#pragma unroll
            for (int t = 0; t < af.num_elements; t++) af.x[t] = wmma::__float_to_tf32(af.x[t]);
#pragma unroll
            for (int t = 0; t < bf.num_elements; t++) bf.x[t] = wmma::__float_to_tf32(bf.x[t]);
            wmma::mma_sync(oacc, af, bf, oacc);
        }
        wmma::store_matrix_sync(
            &g_A[((size_t)(b * SEQ + s0 + wr * 16)) * INNER + h * DHEAD + ch * 32 + wc * 16],
            oacc, INNER, wmma::mem_row_major);
        __syncthreads();
    }
}

// ---------------- launch ----------------
extern "C" void kernel_launch(void* const* d_in, const int* in_sizes, int n_in,
                              void* d_out, int out_size)
{
    const float* x       = (const float*)d_in[0];
    const float* context = (const float*)d_in[1];
    const float* Wq      = (const float*)d_in[2];
    const float* Wk      = (const float*)d_in[3];
    const float* Wv      = (const float*)d_in[4];
    const float* Wo      = (const float*)d_in[5];
    const float* bo      = (const float*)d_in[6];
    float* out = (float*)d_out;

    cudaFuncSetAttribute(gemm_q_fast, cudaFuncAttributeMaxDynamicSharedMemorySize, GEMM_SMEM_BYTES);
    cudaFuncSetAttribute(gemm_o_fast, cudaFuncAttributeMaxDynamicSharedMemorySize, GEMM_SMEM_BYTES);

    // Q = x @ Wq : (32768,1024)@(1024,512), tile 128x256
    gemm_q_fast<<<dim3(INNER / FBN, MX / FBM), 512, GEMM_SMEM_BYTES>>>(x, Wq);
    // K,V = context @ Wk/Wv : fused single launch
    gemm_kv_kernel<<<dim3(INNER / GM_BN, (MC + GM_BM - 1) / GM_BM, 2), 128>>>(context, Wk, Wv);
    // attention
    attn_wmma_kernel<<<dim3(SEQ / BQ, HEADS, BATCH), 256>>>();
    // out = A @ Wo + bo : (32768,512)@(512,1024), tile 128x256
    gemm_o_fast<<<dim3(QDIM / FBN, MX / FBM), 512, GEMM_SMEM_BYTES>>>(Wo, bo, out);
}

// round 17
// speedup vs baseline: 1.6741x; 1.6741x over previous
#include <cuda_runtime.h>
#include <cuda_bf16.h>
#include <mma.h>

using namespace nvcuda;

// ---------------- problem constants ----------------
#define BATCH 8
#define SEQ 4096
#define CTX_L 77
#define QDIM 1024
#define CDIM 768
#define HEADS 8
#define DHEAD 64
#define INNER 512          // HEADS * DHEAD

#define MX (BATCH * SEQ)     // 32768
#define MC (BATCH * CTX_L)   // 616

// ---------------- scratch ----------------
__device__ float g_Q[BATCH * SEQ * INNER];      // 64 MiB
__device__ float g_K[BATCH * CTX_L * INNER];
__device__ float g_V[BATCH * CTX_L * INNER];
__device__ float g_A[BATCH * SEQ * INNER];      // 64 MiB (tf32-rounded at write)
__device__ float g_X[MX * QDIM];                // 128 MiB, tf32-rounded x
__device__ float g_Wq_r[QDIM * INNER];          // tf32-rounded Wq
__device__ float g_Wo_r[INNER * QDIM];          // tf32-rounded Wo

// ---------------- cp.async helpers ----------------
__device__ __forceinline__ unsigned smem_u32(const void* p) {
    return (unsigned)__cvta_generic_to_shared(p);
}
__device__ __forceinline__ void cp16(unsigned s, const void* g) {
    asm volatile("cp.async.cg.shared.global [%0], [%1], 16;\n" :: "r"(s), "l"(g));
}
#define CP_COMMIT() asm volatile("cp.async.commit_group;" ::: "memory")
#define CP_WAIT(n)  asm volatile("cp.async.wait_group %0;" :: "n"(n) : "memory")

// ---------------- tf32 pre-round kernels (device-global dst) ----------------
__global__ __launch_bounds__(256) void round_x_kernel(const float* __restrict__ src, int n4)
{
    int i = blockIdx.x * 256 + threadIdx.x;
    if (i < n4) {
        float4 v = ((const float4*)src)[i];
        v.x = wmma::__float_to_tf32(v.x);
        v.y = wmma::__float_to_tf32(v.y);
        v.z = wmma::__float_to_tf32(v.z);
        v.w = wmma::__float_to_tf32(v.w);
        ((float4*)g_X)[i] = v;
    }
}
__global__ __launch_bounds__(256) void round_w_kernel(
    const float* __restrict__ src, int which, int n4)
{
    int i = blockIdx.x * 256 + threadIdx.x;
    if (i < n4) {
        float4 v = ((const float4*)src)[i];
        v.x = wmma::__float_to_tf32(v.x);
        v.y = wmma::__float_to_tf32(v.y);
        v.z = wmma::__float_to_tf32(v.z);
        v.w = wmma::__float_to_tf32(v.w);
        float4* dst = which ? (float4*)g_Wo_r : (float4*)g_Wq_r;
        dst[i] = v;
    }
}

// =====================================================================
// FAST GEMM (all operands pre-rounded tf32 => ZERO cvt in mainloop):
// C[M,N] = A[M,K] @ B[K,N] (+bias). M%128==0, N%128==0, K%32==0, K/32>=3.
// Tile 128x128x32, 256 threads (8 warps, warp tile 32x64), 3-stage
// cp.async, ONE __syncthreads per iteration.
// Dynamic smem: 3*(128*40 + 32*136)*4 = 113664 bytes (2 CTA/SM = 222KB).
// =====================================================================
#define FBM 128
#define FBN 128
#define FBK 32
#define ALD 40     // A row stride (160B, 32B multiple)
#define BLD 136    // B row stride (544B, 32B multiple)
#define A_STAGE (FBM * ALD)   // 5120 floats
#define B_STAGE (FBK * BLD)   // 4352 floats
#define GEMM_SMEM_BYTES ((3 * (A_STAGE + B_STAGE)) * 4)  // 113664

__device__ __forceinline__ void gemm_fast_body(
    const float* __restrict__ A, const float* __restrict__ B,
    float* __restrict__ C, const float* __restrict__ bias,
    int M, int N, int K)
{
    extern __shared__ float dsm[];
    float* As = dsm;                 // [3][128][ALD]
    float* Bs = dsm + 3 * A_STAGE;   // [3][32][BLD]

    const int tid  = threadIdx.x;
    const int warp = tid >> 5;
    const int wm   = warp >> 1;   // 0..3 (32-row strip)
    const int wn   = warp & 1;    // 0..1 (64-col strip)
    const int row0 = blockIdx.y * FBM;
    const int col0 = blockIdx.x * FBN;

    wmma::fragment<wmma::accumulator, 16, 16, 8, float> acc[2][4];
    if (bias) {
        for (int i = tid; i < 16 * FBN; i += 256) {
            int r = i >> 7, c = i & 127;
            Bs[r * BLD + c] = bias[col0 + c];
        }
        __syncthreads();
#pragma unroll
        for (int i = 0; i < 2; i++)
#pragma unroll
            for (int j = 0; j < 4; j++)
                wmma::load_matrix_sync(acc[i][j], &Bs[wn * 64 + j * 16],
                                       BLD, wmma::mem_row_major);
        __syncthreads();
    } else {
#pragma unroll
        for (int i = 0; i < 2; i++)
#pragma unroll
            for (int j = 0; j < 4; j++)
                wmma::fill_fragment(acc[i][j], 0.0f);
    }

    auto load_stage = [&](int st, int k0) {
        float* Ad = As + st * A_STAGE;
        float* Bd = Bs + st * B_STAGE;
        // A: 128x32 = 1024 float4, 4 per thread
#pragma unroll
        for (int i = 0; i < 4; i++) {
            int slot = tid + i * 256;
            int r = slot >> 3, c4 = (slot & 7) * 4;
            cp16(smem_u32(&Ad[r * ALD + c4]),
                 A + (size_t)(row0 + r) * K + k0 + c4);
        }
        // B: 32x128 = 1024 float4, 4 per thread
#pragma unroll
        for (int i = 0; i < 4; i++) {
            int slot = tid + i * 256;
            int r = slot >> 5, c4 = (slot & 31) * 4;
            cp16(smem_u32(&Bd[r * BLD + c4]),
                 B + (size_t)(k0 + r) * N + col0 + c4);
        }
        CP_COMMIT();
    };

    const int nIter = K / FBK;
    load_stage(0, 0);
    load_stage(1, FBK);

    int st = 0;
    for (int it = 0; it < nIter; ++it) {
        if (it == nIter - 1) { CP_WAIT(0); } else { CP_WAIT(1); }
        __syncthreads();   // stage st arrived; all warps done reading (it-1)%3
        if (it + 2 < nIter) {
            int tgt = st + 2; if (tgt >= 3) tgt -= 3;
            load_stage(tgt, (it + 2) * FBK);
        }

        const float* Ab = As + st * A_STAGE;
        const float* Bb = Bs + st * B_STAGE;
#pragma unroll
        for (int kk = 0; kk < 4; kk++) {
            wmma::fragment<wmma::matrix_a, 16, 16, 8, wmma::precision::tf32, wmma::row_major> af[2];
            wmma::fragment<wmma::matrix_b, 16, 16, 8, wmma::precision::tf32, wmma::row_major> bf[4];
            wmma::load_matrix_sync(af[0], &Ab[(wm * 32) * ALD + kk * 8],      ALD);
            wmma::load_matrix_sync(af[1], &Ab[(wm * 32 + 16) * ALD + kk * 8], ALD);
#pragma unroll
            for (int j = 0; j < 4; j++)
                wmma::load_matrix_sync(bf[j], &Bb[(kk * 8) * BLD + wn * 64 + j * 16], BLD);
            // operands pre-rounded to tf32: HW truncation is identity, no cvt
#pragma unroll
            for (int i = 0; i < 2; i++)
#pragma unroll
                for (int j = 0; j < 4; j++)
                    wmma::mma_sync(acc[i][j], af[i], bf[j], acc[i][j]);
        }
        if (++st == 3) st = 0;
    }

    // epilogue: fragments straight to GMEM
#pragma unroll
    for (int i = 0; i < 2; i++)
#pragma unroll
        for (int j = 0; j < 4; j++)
            wmma::store_matrix_sync(
                C + (size_t)(row0 + wm * 32 + i * 16) * N + col0 + wn * 64 + j * 16,
                acc[i][j], N, wmma::mem_row_major);
}

__global__ __launch_bounds__(256, 2) void gemm_q_fast()
{
    gemm_fast_body(g_X, g_Wq_r, g_Q, nullptr, MX, INNER, QDIM);
}
__global__ __launch_bounds__(256, 2) void gemm_o_fast(
    const float* __restrict__ bo, float* __restrict__ out)
{
    gemm_fast_body(g_A, g_Wo_r, out, bo, MX, QDIM, INNER);
}

// =====================================================================
// fused K/V projection (M=616): 64x64x32, 128 threads; blockIdx.z picks
// (Wk -> g_K) or (Wv -> g_V).
// =====================================================================
#define GM_BM 64
#define GM_BN 64
#define GM_BK 32
#define GM_PADA 8
#define GM_PADB 8

__global__ __launch_bounds__(128) void gemm_kv_kernel(
    const float* __restrict__ ctx,
    const float* __restrict__ Wk, const float* __restrict__ Wv)
{
    const float* B = blockIdx.z ? Wv : Wk;
    float* C = blockIdx.z ? g_V : g_K;
    const int M = MC, N = INNER, K = CDIM;

    __shared__ float As[GM_BM][GM_BK + GM_PADA];
    __shared__ float Bs[GM_BK][GM_BN + GM_PADB];
    __shared__ float Cs[GM_BM][GM_BN + 4];

    const int tid  = threadIdx.x;
    const int warp = tid >> 5;
    const int wm   = warp >> 1;
    const int wn   = warp & 1;
    const int row0 = blockIdx.y * GM_BM;
    const int col0 = blockIdx.x * GM_BN;

    wmma::fragment<wmma::accumulator, 16, 16, 8, float> acc[2][2];
#pragma unroll
    for (int i = 0; i < 2; i++)
#pragma unroll
        for (int j = 0; j < 2; j++)
            wmma::fill_fragment(acc[i][j], 0.0f);

    for (int k0 = 0; k0 < K; k0 += GM_BK) {
#pragma unroll
        for (int i = 0; i < 4; i++) {
            int slot = tid + i * 128;
            int r = slot >> 3, c4 = (slot & 7) * 4;
            int grow = row0 + r;
            float4 v = make_float4(0.f, 0.f, 0.f, 0.f);
            if (grow < M)
                v = *(const float4*)(ctx + (size_t)grow * K + k0 + c4);
            *(float4*)&As[r][c4] = v;
        }
#pragma unroll
        for (int i = 0; i < 4; i++) {
            int slot = tid + i * 128;
            int r = slot >> 4, c4 = (slot & 15) * 4;
            float4 v = *(const float4*)(B + (size_t)(k0 + r) * N + col0 + c4);
            *(float4*)&Bs[r][c4] = v;
        }
        __syncthreads();

#pragma unroll
        for (int kk = 0; kk < 4; kk++) {
            wmma::fragment<wmma::matrix_a, 16, 16, 8, wmma::precision::tf32, wmma::row_major> a0, a1;
            wmma::fragment<wmma::matrix_b, 16, 16, 8, wmma::precision::tf32, wmma::row_major> b0, b1;
            wmma::load_matrix_sync(a0, &As[wm * 32][kk * 8],      GM_BK + GM_PADA);
            wmma::load_matrix_sync(a1, &As[wm * 32 + 16][kk * 8], GM_BK + GM_PADA);
            wmma::load_matrix_sync(b0, &Bs[kk * 8][wn * 32],      GM_BN + GM_PADB);
            wmma::load_matrix_sync(b1, &Bs[kk * 8][wn * 32 + 16], GM_BN + GM_PADB);
#pragma unroll
            for (int t = 0; t < a0.num_elements; t++) {
                a0.x[t] = wmma::__float_to_tf32(a0.x[t]);
                a1.x[t] = wmma::__float_to_tf32(a1.x[t]);
            }
#pragma unroll
            for (int t = 0; t < b0.num_elements; t++) {
                b0.x[t] = wmma::__float_to_tf32(b0.x[t]);
                b1.x[t] = wmma::__float_to_tf32(b1.x[t]);
            }
            wmma::mma_sync(acc[0][0], a0, b0, acc[0][0]);
            wmma::mma_sync(acc[0][1], a0, b1, acc[0][1]);
            wmma::mma_sync(acc[1][0], a1, b0, acc[1][0]);
            wmma::mma_sync(acc[1][1], a1, b1, acc[1][1]);
        }
        __syncthreads();
    }

#pragma unroll
    for (int i = 0; i < 2; i++)
#pragma unroll
        for (int j = 0; j < 2; j++)
            wmma::store_matrix_sync(&Cs[wm * 32 + i * 16][wn * 32 + j * 16],
                                    acc[i][j], GM_BN + 4, wmma::mem_row_major);
    __syncthreads();

#pragma unroll
    for (int i = 0; i < 8; i++) {
        int slot = tid + i * 128;
        int r = slot >> 4, c4 = (slot & 15) * 4;
        int grow = row0 + r;
        if (grow < M)
            *(float4*)(C + (size_t)grow * N + col0 + c4) = *(float4*)&Cs[r][c4];
    }
}

// =====================================================================
// Tensor-core cross-attention (R12 version; output tf32-rounded so
// O-proj needs no cvt).
// =====================================================================
#define BQ   64
#define LPAD 96
#define QLD  68
#define SLD  100
#define VLD  36

__global__ __launch_bounds__(256) void attn_wmma_kernel()
{
    __shared__ float sm[10880];
    float* Qs = sm;
    float* Ks = sm + BQ * QLD;
    float* Ss = sm;
    float* Vs = sm + BQ * SLD;

    const int b  = blockIdx.z;
    const int h  = blockIdx.y;
    const int s0 = blockIdx.x * BQ;
    const int tid  = threadIdx.x;
    const int warp = tid >> 5;
    const int wr   = warp >> 1;
    const int wc   = warp & 1;

    for (int idx = tid; idx < BQ * 16; idx += 256) {
        int r = idx >> 4, c4 = (idx & 15) << 2;
        *(float4*)&Qs[r * QLD + c4] =
            *(const float4*)&g_Q[((size_t)(b * SEQ + s0 + r)) * INNER + h * DHEAD + c4];
    }
    for (int idx = tid; idx < CTX_L * 16; idx += 256) {
        int r = idx >> 4, c4 = (idx & 15) << 2;
        *(float4*)&Ks[r * QLD + c4] =
            *(const float4*)&g_K[((size_t)(b * CTX_L + r)) * INNER + h * DHEAD + c4];
    }
    __syncthreads();

    const int ct0 = wc ? 3 : 0;
    const int nct = wc ? 2 : 3;
    wmma::fragment<wmma::accumulator, 16, 16, 8, float> sacc[3];
#pragma unroll
    for (int j = 0; j < 3; j++) wmma::fill_fragment(sacc[j], 0.0f);

#pragma unroll
    for (int k = 0; k < 8; k++) {
        wmma::fragment<wmma::matrix_a, 16, 16, 8, wmma::precision::tf32, wmma::row_major> af;
        wmma::load_matrix_sync(af, &Qs[(wr * 16) * QLD + k * 8], QLD);
#pragma unroll
        for (int t = 0; t < af.num_elements; t++) af.x[t] = wmma::__float_to_tf32(af.x[t]);
#pragma unroll
        for (int j = 0; j < 3; j++) {
            if (j >= nct) break;
            wmma::fragment<wmma::matrix_b, 16, 16, 8, wmma::precision::tf32, wmma::col_major> bf;
            wmma::load_matrix_sync(bf, &Ks[((ct0 + j) * 16) * QLD + k * 8], QLD);
#pragma unroll
            for (int t = 0; t < bf.num_elements; t++) bf.x[t] = wmma::__float_to_tf32(bf.x[t]);
            wmma::mma_sync(sacc[j], af, bf, sacc[j]);
        }
    }
#pragma unroll
    for (int j = 0; j < 3; j++)
#pragma unroll
        for (int t = 0; t < sacc[j].num_elements; t++) sacc[j].x[t] *= 0.125f;

    __syncthreads();
#pragma unroll
    for (int j = 0; j < 3; j++) {
        if (j >= nct) break;
        wmma::store_matrix_sync(&Ss[(wr * 16) * SLD + (ct0 + j) * 16], sacc[j],
                                SLD, wmma::mem_row_major);
    }
    __syncthreads();

    {
        const int row = tid >> 2, p = tid & 3;
        float* srow = &Ss[row * SLD];
        const int c0 = p * 24, c1 = c0 + 24;
        float mx = -1e30f;
        for (int c = c0; c < c1 && c < CTX_L; c++) mx = fmaxf(mx, srow[c]);
        mx = fmaxf(mx, __shfl_xor_sync(0xffffffffu, mx, 1));
        mx = fmaxf(mx, __shfl_xor_sync(0xffffffffu, mx, 2));
        float sum = 0.f;
        float ebuf[24];
#pragma unroll
        for (int i = 0; i < 24; i++) {
            int c = c0 + i;
            float e = (c < CTX_L) ? __expf(srow[c] - mx) : 0.f;
            ebuf[i] = e; sum += e;
        }
        sum += __shfl_xor_sync(0xffffffffu, sum, 1);
        sum += __shfl_xor_sync(0xffffffffu, sum, 2);
        const float inv = 1.f / sum;
#pragma unroll
        for (int i = 0; i < 24; i++) srow[c0 + i] = ebuf[i] * inv;
    }
    __syncthreads();

#pragma unroll
    for (int ch = 0; ch < 2; ch++) {
        for (int idx = tid; idx < CTX_L * 8; idx += 256) {
            int r = idx >> 3, c4 = (idx & 7) << 2;
            *(float4*)&Vs[r * VLD + c4] =
                *(const float4*)&g_V[((size_t)(b * CTX_L + r)) * INNER + h * DHEAD + ch * 32 + c4];
        }
        for (int idx = tid; idx < (LPAD - CTX_L) * 8; idx += 256) {
            int r = CTX_L + (idx >> 3), c4 = (idx & 7) << 2;
            *(float4*)&Vs[r * VLD + c4] = make_float4(0.f, 0.f, 0.f, 0.f);
        }
        __syncthreads();

        wmma::fragment<wmma::accumulator, 16, 16, 8, float> oacc;
        wmma::fill_fragment(oacc, 0.0f);
#pragma unroll
        for (int k = 0; k < LPAD / 8; k++) {
            wmma::fragment<wmma::matrix_a, 16, 16, 8, wmma::precision::tf32, wmma::row_major> af;
            wmma::fragment<wmma::matrix_b, 16, 16, 8, wmma::precision::tf32, wmma::row_major> bf;
            wmma::load_matrix_sync(af, &Ss[(wr * 16) * SLD + k * 8], SLD);
            wmma::load_matrix_sync(bf, &Vs[(k * 8) * VLD + wc * 16], VLD);
#pragma unroll
            for (int t = 0; t < af.num_elements; t++) af.x[t] = wmma::__float_to_tf32(af.x[t]);
#pragma unroll
            for (int t = 0; t < bf.num_elements; t++) bf.x[t] = wmma::__float_to_tf32(bf.x[t]);
            wmma::mma_sync(oacc, af, bf, oacc);
        }
        // round output to tf32: O-proj mainloop then needs zero cvts
#pragma unroll
        for (int t = 0; t < oacc.num_elements; t++)
            oacc.x[t] = wmma::__float_to_tf32(oacc.x[t]);
        wmma::store_matrix_sync(
            &g_A[((size_t)(b * SEQ + s0 + wr * 16)) * INNER + h * DHEAD + ch * 32 + wc * 16],
            oacc, INNER, wmma::mem_row_major);
        __syncthreads();
    }
}

// ---------------- launch ----------------
extern "C" void kernel_launch(void* const* d_in, const int* in_sizes, int n_in,
                              void* d_out, int out_size)
{
    const float* x       = (const float*)d_in[0];
    const float* context = (const float*)d_in[1];
    const float* Wq      = (const float*)d_in[2];
    const float* Wk      = (const float*)d_in[3];
    const float* Wv      = (const float*)d_in[4];
    const float* Wo      = (const float*)d_in[5];
    const float* bo      = (const float*)d_in[6];
    float* out = (float*)d_out;

    cudaFuncSetAttribute(gemm_q_fast, cudaFuncAttributeMaxDynamicSharedMemorySize, GEMM_SMEM_BYTES);
    cudaFuncSetAttribute(gemm_o_fast, cudaFuncAttributeMaxDynamicSharedMemorySize, GEMM_SMEM_BYTES);

    // pre-round operands to tf32 (removes ALL cvts from GEMM mainloops)
    round_x_kernel<<<(MX * QDIM / 4 + 255) / 256, 256>>>(x, MX * QDIM / 4);
    round_w_kernel<<<(QDIM * INNER / 4 + 255) / 256, 256>>>(Wq, 0, QDIM * INNER / 4);
    round_w_kernel<<<(QDIM * INNER / 4 + 255) / 256, 256>>>(Wo, 1, QDIM * INNER / 4);

    // Q = x @ Wq : (32768,1024)@(1024,512)
    gemm_q_fast<<<dim3(INNER / FBN, MX / FBM), 256, GEMM_SMEM_BYTES>>>();
    // K,V = context @ Wk/Wv : fused single launch
    gemm_kv_kernel<<<dim3(INNER / GM_BN, (MC + GM_BM - 1) / GM_BM, 2), 128>>>(context, Wk, Wv);
    // attention
    attn_wmma_kernel<<<dim3(SEQ / BQ, HEADS, BATCH), 256>>>();
    // out = A @ Wo + bo : (32768,512)@(512,1024)
    gemm_o_fast<<<dim3(QDIM / FBN, MX / FBM), 256, GEMM_SMEM_BYTES>>>(bo, out);
}